// round 5
// baseline (speedup 1.0000x reference)
#include <cuda_runtime.h>
#include <cuda_bf16.h>

#define N_NODES 50000
#define N_EDGES 500000
#define N_GRAPHS 100
#define DD 146
#define NS 148          // padded row stride (float), 592B = 37 x float4
#define BN_EPS 1e-5f

// ---------------- scratch (static device globals; no allocation) ----------------
__device__ __align__(16) float g_h   [N_NODES * NS];
__device__ __align__(16) float g_hW  [N_NODES * NS];
__device__ __align__(16) float g_agg [N_NODES * NS];
__device__ __align__(16) float g_hacc[N_NODES * NS];
__device__ float g_norm_src[N_NODES];
__device__ float g_norm_dst[N_NODES];
__device__ float g_counts[N_GRAPHS];
__device__ __align__(16) float g_hg[N_GRAPHS * DD];
__device__ float g_bnsum[2 * NS];   // [0:NS) col sums, [NS:2NS) col sumsq
__device__ float g_mean[NS];
__device__ float g_rstd[NS];

// ---------------- helpers ----------------
__device__ __forceinline__ void red_add_v4(float4* p, float4 v) {
    asm volatile("red.global.add.v4.f32 [%0], {%1,%2,%3,%4};"
                 :: "l"(p), "f"(v.x), "f"(v.y), "f"(v.z), "f"(v.w) : "memory");
}

// ---------------- init / zero kernels ----------------
__global__ void zero_init_kernel() {
    int idx = blockIdx.x * blockDim.x + threadIdx.x;
    int stride = gridDim.x * blockDim.x;
    const float4 z4 = make_float4(0.f, 0.f, 0.f, 0.f);
    const int n4 = N_NODES * NS / 4;
    float4* hacc4 = reinterpret_cast<float4*>(g_hacc);
    for (int i = idx; i < n4; i += stride) hacc4[i] = z4;
    for (int i = idx; i < N_NODES; i += stride) { g_norm_src[i] = 0.f; g_norm_dst[i] = 0.f; }
    for (int i = idx; i < N_GRAPHS * DD; i += stride) g_hg[i] = 0.f;
    for (int i = idx; i < N_GRAPHS; i += stride) g_counts[i] = 0.f;
}

__global__ void zero_agg_kernel() {
    int idx = blockIdx.x * blockDim.x + threadIdx.x;
    int stride = gridDim.x * blockDim.x;
    const float4 z4 = make_float4(0.f, 0.f, 0.f, 0.f);
    const int n4 = N_NODES * NS / 4;
    float4* agg4 = reinterpret_cast<float4*>(g_agg);
    for (int i = idx; i < n4; i += stride) agg4[i] = z4;
    // FIX (R4): grid-stride loop — previous version only zeroed the first 256
    // of 296 entries, leaving sumsq slots for features 108..145 accumulating
    // across layers (the 6.7e-2 rel_err culprit).
    for (int i = idx; i < 2 * NS; i += stride) g_bnsum[i] = 0.f;
}

// ---------------- degree norms + graph counts ----------------
__global__ void deg_kernel(const int* __restrict__ src, const int* __restrict__ dst) {
    int idx = blockIdx.x * blockDim.x + threadIdx.x;
    int stride = gridDim.x * blockDim.x;
    for (int e = idx; e < N_EDGES; e += stride) {
        atomicAdd(&g_norm_src[src[e]], 1.0f);
        atomicAdd(&g_norm_dst[dst[e]], 1.0f);
    }
}

__global__ void deg_finalize_kernel(const int* __restrict__ graph_ids) {
    int idx = blockIdx.x * blockDim.x + threadIdx.x;
    int stride = gridDim.x * blockDim.x;
    for (int i = idx; i < N_NODES; i += stride) {
        g_norm_src[i] = rsqrtf(fmaxf(g_norm_src[i], 1.0f));
        g_norm_dst[i] = rsqrtf(fmaxf(g_norm_dst[i], 1.0f));
        atomicAdd(&g_counts[graph_ids[i]], 1.0f);
    }
}

// ---------------- GEMM: C[M,NS] = diag(scale?) * A[M,146] @ W[146,146] (+bias) ----------------
// Block: 64 rows x all 148 output cols. Full W in smem (padded to 160 cols),
// A tile transposed in smem (pad 68 so float4 loads stay 16B aligned).
// 256 threads = 16x16, each computes a 4(row) x 10(col) micro-tile.
#define GEMM_BM 64
#define GEMM_SMEM_FLOATS (146 * 160 + 146 * 68)
#define GEMM_SMEM_BYTES  (GEMM_SMEM_FLOATS * 4)

__global__ void gemm_kernel(const float* __restrict__ Aext, int use_gh,
                            const float* __restrict__ W, const float* __restrict__ bias,
                            int use_scale, int out_hw)
{
    extern __shared__ float smem[];
    float* Ws = smem;                 // [146][160]
    float* At = smem + 146 * 160;     // [146][68] (transposed A tile)

    const float* A = use_gh ? g_h : Aext;
    const int lda = use_gh ? NS : DD;
    float* C = out_hw ? g_hW : g_h;
    const int tid = threadIdx.x;

    // stage W (+ zero pad cols 146..159)
    for (int i = tid; i < 146 * 146; i += 256) {
        int k = i / 146, n = i - k * 146;
        Ws[k * 160 + n] = W[i];
    }
    for (int i = tid; i < 146 * 14; i += 256) {
        int k = i / 14, n = 146 + (i - k * 14);
        Ws[k * 160 + n] = 0.f;
    }
    // stage A tile transposed, apply row scale
    const int row0 = blockIdx.x * GEMM_BM;
    for (int i = tid; i < GEMM_BM * 146; i += 256) {
        int r = i / 146, k = i - r * 146;
        int row = row0 + r;
        float v = 0.f;
        if (row < N_NODES) {
            v = A[(size_t)row * lda + k];
            if (use_scale) v *= g_norm_src[row];
        }
        At[k * 68 + r] = v;
    }
    __syncthreads();

    const int tx = tid & 15;     // col group: cols tx*10 .. tx*10+9
    const int ty = tid >> 4;     // row group: rows ty*4 .. ty*4+3
    float acc[4][10];
#pragma unroll
    for (int i = 0; i < 4; i++)
#pragma unroll
        for (int j = 0; j < 10; j++) acc[i][j] = 0.f;

    const float4* At4 = reinterpret_cast<const float4*>(At);   // row k at idx k*17
    const float2* Ws2 = reinterpret_cast<const float2*>(Ws);   // row k at idx k*80

#pragma unroll 2
    for (int k = 0; k < 146; k++) {
        float4 a4 = At4[k * 17 + ty];
        float av[4] = {a4.x, a4.y, a4.z, a4.w};
#pragma unroll
        for (int j = 0; j < 5; j++) {
            float2 w = Ws2[k * 80 + tx * 5 + j];
#pragma unroll
            for (int i = 0; i < 4; i++) {
                acc[i][2 * j]     += av[i] * w.x;
                acc[i][2 * j + 1] += av[i] * w.y;
            }
        }
    }

#pragma unroll
    for (int i = 0; i < 4; i++) {
        int row = row0 + ty * 4 + i;
        if (row >= N_NODES) continue;
        float* crow = C + (size_t)row * NS;
#pragma unroll
        for (int jj = 0; jj < 10; jj++) {
            int col = tx * 10 + jj;
            if (col < NS) {
                float v = 0.f;
                if (col < DD) {
                    v = acc[i][jj];
                    if (bias) v += bias[col];
                }
                crow[col] = v;
            }
        }
    }
}

// ---------------- edge scatter: agg[dst] += hW[src], vectorized red.v4 ----------------
__global__ void scatter_kernel(const int* __restrict__ src, const int* __restrict__ dst) {
    const int warp_id = (blockIdx.x * blockDim.x + threadIdx.x) >> 5;
    const int lane = threadIdx.x & 31;
    if (warp_id >= N_EDGES) return;
    const int s = __ldg(&src[warp_id]);
    const int d = __ldg(&dst[warp_id]);
    const float4* srow = reinterpret_cast<const float4*>(g_hW + (size_t)s * NS);
    float4* drow = reinterpret_cast<float4*>(g_agg + (size_t)d * NS);
    float4 v = __ldg(&srow[lane]);
    red_add_v4(drow + lane, v);
    if (lane < 5) {
        float4 v2 = __ldg(&srow[32 + lane]);
        red_add_v4(drow + 32 + lane, v2);
    }
}

// ---------------- finalize 1: agg = (agg*norm_dst + b)*snorm (in place) + BN col sums ----------------
// blockDim 160, threadIdx.x = feature column; column layout -> coalesced row reads.
__global__ void finalize1_kernel(const float* __restrict__ snorm,
                                 const float* __restrict__ bs, int layer)
{
    const int f = threadIdx.x;
    const bool active = (f < DD);
    const float b = active ? __ldg(&bs[layer * DD + f]) : 0.f;
    const int per = (N_NODES + gridDim.x - 1) / gridDim.x;
    const int s = blockIdx.x * per;
    const int e = min(s + per, N_NODES);
    float sum = 0.f, sumsq = 0.f;
#pragma unroll 4
    for (int node = s; node < e; node++) {
        float nd = __ldg(&g_norm_dst[node]);
        float sn = __ldg(&snorm[node]);
        if (active) {
            size_t idx = (size_t)node * NS + f;
            float v = (g_agg[idx] * nd + b) * sn;
            g_agg[idx] = v;
            sum += v;
            sumsq += v * v;
        }
    }
    if (active) {
        atomicAdd(&g_bnsum[f], sum);
        atomicAdd(&g_bnsum[NS + f], sumsq);
    }
}

__global__ void bn_stats_kernel() {
    const int f = threadIdx.x;
    if (f >= DD) return;
    const float invN = 1.0f / (float)N_NODES;
    float mean = g_bnsum[f] * invN;
    float var = g_bnsum[NS + f] * invN - mean * mean;
    var = fmaxf(var, 0.f);
    g_mean[f] = mean;
    g_rstd[f] = rsqrtf(var + BN_EPS);
}

// ---------------- finalize 2: h = h + relu(BN(agg)); hacc += h ----------------
__global__ void finalize2_kernel(const float* __restrict__ gammas,
                                 const float* __restrict__ betas, int layer)
{
    const int f = threadIdx.x;
    const bool active = (f < DD);
    float mean = 0.f, rstd = 0.f, ga = 0.f, be = 0.f;
    if (active) {
        mean = g_mean[f];
        rstd = g_rstd[f];
        ga = __ldg(&gammas[layer * DD + f]);
        be = __ldg(&betas[layer * DD + f]);
    }
    const int per = (N_NODES + gridDim.x - 1) / gridDim.x;
    const int s = blockIdx.x * per;
    const int e = min(s + per, N_NODES);
#pragma unroll 4
    for (int node = s; node < e; node++) {
        if (active) {
            size_t idx = (size_t)node * NS + f;
            float bn = (g_agg[idx] - mean) * rstd * ga + be;
            float r = fmaxf(bn, 0.f);
            float hnew = g_h[idx] + r;
            g_h[idx] = hnew;
            g_hacc[idx] += hnew;
        }
    }
}

// ---------------- hg = segment_sum(hacc, graph_ids) (raw sums; / counts in readout) ----------------
// graph_ids are sorted -> run-length detection, flush per graph change. Few atomics total.
__global__ void hg_kernel(const int* __restrict__ graph_ids) {
    const int f = threadIdx.x;
    const bool active = (f < DD);
    const int per = (N_NODES + gridDim.x - 1) / gridDim.x;
    const int s = blockIdx.x * per;
    const int e = min(s + per, N_NODES);
    int cur = -1;
    float acc = 0.f;
    for (int node = s; node < e; node++) {
        int g = __ldg(&graph_ids[node]);
        if (g != cur) {
            if (cur >= 0 && active) atomicAdd(&g_hg[cur * DD + f], acc);
            cur = g;
            acc = 0.f;
        }
        if (active) acc += g_hacc[(size_t)node * NS + f];
    }
    if (cur >= 0 && active) atomicAdd(&g_hg[cur * DD + f], acc);
}

// ---------------- MLP readout: 146 -> 73 -> 36 -> 10, one block per graph ----------------
__global__ void readout_kernel(const float* __restrict__ W_r0, const float* __restrict__ b_r0,
                               const float* __restrict__ W_r1, const float* __restrict__ b_r1,
                               const float* __restrict__ W_r2, const float* __restrict__ b_r2,
                               float* __restrict__ out)
{
    __shared__ float sh[DD + 73 + 36];
    const int g = blockIdx.x;
    const int t = threadIdx.x;
    const float inv = 1.0f / fmaxf(g_counts[g], 1.0f);
    for (int k = t; k < DD; k += blockDim.x) sh[k] = g_hg[g * DD + k] * inv;
    __syncthreads();
    if (t < 73) {
        float a = b_r0[t];
        for (int k = 0; k < DD; k++) a += sh[k] * W_r0[k * 73 + t];
        sh[DD + t] = fmaxf(a, 0.f);
    }
    __syncthreads();
    if (t < 36) {
        float a = b_r1[t];
        for (int k = 0; k < 73; k++) a += sh[DD + k] * W_r1[k * 36 + t];
        sh[DD + 73 + t] = fmaxf(a, 0.f);
    }
    __syncthreads();
    if (t < 10) {
        float a = b_r2[t];
        for (int k = 0; k < 36; k++) a += sh[DD + 73 + k] * W_r2[k * 10 + t];
        out[g * 10 + t] = a;
    }
}

// ---------------- launch ----------------
extern "C" void kernel_launch(void* const* d_in, const int* in_sizes, int n_in,
                              void* d_out, int out_size)
{
    const float* nodes_feat = (const float*)d_in[0];
    const float* snorm      = (const float*)d_in[1];
    const float* W_emb      = (const float*)d_in[2];
    const float* b_emb      = (const float*)d_in[3];
    const float* Ws         = (const float*)d_in[4];
    const float* bs         = (const float*)d_in[5];
    const float* gammas     = (const float*)d_in[6];
    const float* betas      = (const float*)d_in[7];
    const float* W_r0       = (const float*)d_in[8];
    const float* b_r0       = (const float*)d_in[9];
    const float* W_r1       = (const float*)d_in[10];
    const float* b_r1       = (const float*)d_in[11];
    const float* W_r2       = (const float*)d_in[12];
    const float* b_r2       = (const float*)d_in[13];
    const int*   src        = (const int*)d_in[14];
    const int*   dst        = (const int*)d_in[15];
    const int*   gid        = (const int*)d_in[16];
    float* out = (float*)d_out;

    cudaFuncSetAttribute(gemm_kernel, cudaFuncAttributeMaxDynamicSharedMemorySize,
                         GEMM_SMEM_BYTES);

    const int gemm_blocks = (N_NODES + GEMM_BM - 1) / GEMM_BM;        // 782
    const int scatter_blocks = (N_EDGES * 32) / 256;                   // 62500

    zero_init_kernel<<<1024, 256>>>();
    deg_kernel<<<(N_EDGES + 255) / 256, 256>>>(src, dst);
    deg_finalize_kernel<<<(N_NODES + 255) / 256, 256>>>(gid);

    // embedding: h = nodes_feat @ W_emb + b_emb
    gemm_kernel<<<gemm_blocks, 256, GEMM_SMEM_BYTES>>>(nodes_feat, 0, W_emb, b_emb, 0, 0);

    for (int l = 0; l < 4; l++) {
        // hW = (h * norm_src) @ W_l
        gemm_kernel<<<gemm_blocks, 256, GEMM_SMEM_BYTES>>>(nullptr, 1, Ws + l * DD * DD,
                                                           nullptr, 1, 1);
        zero_agg_kernel<<<1024, 256>>>();
        scatter_kernel<<<scatter_blocks, 256>>>(src, dst);
        finalize1_kernel<<<512, 160>>>(snorm, bs, l);
        bn_stats_kernel<<<1, 160>>>();
        finalize2_kernel<<<1024, 160>>>(gammas, betas, l);
    }

    hg_kernel<<<128, 160>>>(gid);
    readout_kernel<<<N_GRAPHS, 128>>>(W_r0, b_r0, W_r1, b_r1, W_r2, b_r2, out);
}